// round 4
// baseline (speedup 1.0000x reference)
#include <cuda_runtime.h>
#include <cuda_bf16.h>

// NURBS surface evaluation, degree 3 x 3, 32x32 control points, uniform
// clamped knots. S*F = 32 surface slices, P = 200000 points each.
//
// Key ideas:
//  * Work in x = 29*u domain: knot values become clamp(k,0,29) integers, so
//    all Cox-de Boor denominators are in {1,2,3} determined solely by the
//    span -> inverse denominators via selects, NO division / MUFU.
//  * Degree-3 recursion intermediates t_r = B2_r / D3_r directly give the
//    derivative basis: dN = (-t0, t0-t1, t1-t2, t2). The global factor
//    (p * 29) on both d_u and d_v cancels under normalize(cross(.,.)).
//  * Control points for one (s,f) slice cached in smem as float4 (xyz,pad),
//    row stride 33 to spread banks; 4x LDS.128 per row, separable
//    accumulation (row partials) to minimize FMA count.
//  * rsqrt via bit hack + 2 Newton iterations (pure FFMA; MUFU pipe on B300
//    is only ~0.5 op/cyc/SM and would dominate at 6.4M points).

#define SFCOUNT 32          // S * F
#define NCP     32
#define ROWS    NCP
#define RSTRIDE 33          // padded row stride in float4 units

__device__ __forceinline__ void eval_basis(float uu, float b[4], float d[4], int& si_out)
{
    float x  = uu * 29.0f;
    float fs = floorf(x);
    int   si = (int)fs;
    si = max(0, min(si, 28));
    fs = (float)si;

    float t  = x - fs;        // left1
    float r1 = 1.0f - t;      // right1

    // x-domain knots (integers, clamped to [0,29])
    float km1 = (float)max(si - 1, 0);
    float km2 = (float)max(si - 2, 0);
    float kp2 = (float)min(si + 2, 29);
    float kp3 = (float)min(si + 3, 29);
    float left2  = x - km1;
    float left3  = x - km2;
    float right2 = kp2 - x;
    float right3 = kp3 - x;

    // Denominators: D20=min(2,si+1), D21=min(2,29-si), D30=min(3,si+1),
    // D31=min(si+2,29)-max(si-1,0), D32=min(3,29-si). All in {1,2,3}.
    bool e0  = (si == 0);
    bool e1  = (si == 1);
    bool e27 = (si == 27);
    bool e28 = (si == 28);
    const float third = 1.0f / 3.0f;
    float inv20 = e0  ? 1.0f : 0.5f;
    float inv21 = e28 ? 1.0f : 0.5f;
    float inv30 = e0  ? 1.0f : (e1  ? 0.5f : third);
    float inv31 = (e0 || e28) ? 0.5f : third;
    float inv32 = e28 ? 1.0f : (e27 ? 0.5f : third);

    // Degree 2 (B1_0 = r1, B1_1 = t)
    float tA  = r1 * inv20;
    float B20 = r1 * tA;
    float sv  = left2 * tA;
    float tB  = t * inv21;
    float B21 = fmaf(right2, tB, sv);
    float B22 = t * tB;

    // Degree 3
    float t0 = B20 * inv30;
    b[0] = r1 * t0;
    sv   = left3 * t0;
    float t1 = B21 * inv31;
    b[1] = fmaf(right2, t1, sv);
    sv   = left2 * t1;
    float t2 = B22 * inv32;
    b[2] = fmaf(right3, t2, sv);
    b[3] = t * t2;

    // Derivative basis (unscaled; global factor cancels in the normal)
    d[0] = -t0;
    d[1] = t0 - t1;
    d[2] = t1 - t2;
    d[3] = t2;

    si_out = si;
}

__global__ __launch_bounds__(256)
void nurbs_kernel(const float* __restrict__ ev,
                  const float* __restrict__ cp,
                  float* __restrict__ out,
                  int P)
{
    __shared__ float4 scp[ROWS * RSTRIDE];   // 16896 B

    const int sf = blockIdx.y;
    const float* cpb = cp + (size_t)sf * (NCP * NCP * 3);

    // Stage this slice's control points into smem as float4 (xyz, 0)
    for (int k = threadIdx.x; k < NCP * NCP; k += blockDim.x) {
        int iu = k >> 5;
        int iv = k & 31;
        float a = cpb[3 * k + 0];
        float bb = cpb[3 * k + 1];
        float c = cpb[3 * k + 2];
        scp[iu * RSTRIDE + iv] = make_float4(a, bb, c, 0.0f);
    }
    __syncthreads();

    const int p = blockIdx.x * blockDim.x + threadIdx.x;
    if (p >= P) return;

    const float2 uv = reinterpret_cast<const float2*>(ev)[(size_t)sf * P + p];

    float bu[4], du[4], bv[4], dv[4];
    int su, sv_;
    eval_basis(uv.x, bu, du, su);
    eval_basis(uv.y, bv, dv, sv_);

    float px = 0.f, py = 0.f, pz = 0.f;     // surface point
    float ax = 0.f, ay = 0.f, az = 0.f;     // d/du (unscaled)
    float cx = 0.f, cy = 0.f, cz = 0.f;     // d/dv (unscaled)

    const float4* rowbase = scp + su * RSTRIDE + sv_;
#pragma unroll
    for (int i = 0; i < 4; i++) {
        const float4* row = rowbase + i * RSTRIDE;
        float4 c0 = row[0];
        float4 c1 = row[1];
        float4 c2 = row[2];
        float4 c3 = row[3];

        // row partials: r = sum_j Nv0_j * cp, q = sum_j Nv1_j * cp
        float rx = fmaf(bv[3], c3.x, fmaf(bv[2], c2.x, fmaf(bv[1], c1.x, bv[0] * c0.x)));
        float ry = fmaf(bv[3], c3.y, fmaf(bv[2], c2.y, fmaf(bv[1], c1.y, bv[0] * c0.y)));
        float rz = fmaf(bv[3], c3.z, fmaf(bv[2], c2.z, fmaf(bv[1], c1.z, bv[0] * c0.z)));
        float qx = fmaf(dv[3], c3.x, fmaf(dv[2], c2.x, fmaf(dv[1], c1.x, dv[0] * c0.x)));
        float qy = fmaf(dv[3], c3.y, fmaf(dv[2], c2.y, fmaf(dv[1], c1.y, dv[0] * c0.y)));
        float qz = fmaf(dv[3], c3.z, fmaf(dv[2], c2.z, fmaf(dv[1], c1.z, dv[0] * c0.z)));

        px = fmaf(bu[i], rx, px);
        py = fmaf(bu[i], ry, py);
        pz = fmaf(bu[i], rz, pz);
        ax = fmaf(du[i], rx, ax);
        ay = fmaf(du[i], ry, ay);
        az = fmaf(du[i], rz, az);
        cx = fmaf(bu[i], qx, cx);
        cy = fmaf(bu[i], qy, cy);
        cz = fmaf(bu[i], qz, cz);
    }

    // normal = normalize(cross(d_u, d_v))
    float nx = fmaf(ay, cz, -(az * cy));
    float ny = fmaf(az, cx, -(ax * cz));
    float nz = fmaf(ax, cy, -(ay * cx));

    float n2 = fmaf(nx, nx, fmaf(ny, ny, nz * nz));
    n2 = fmaxf(n2, 1.0e-30f);
    float h = 0.5f * n2;
    float y = __uint_as_float(0x5f3759dfu - (__float_as_uint(n2) >> 1));
    y = y * fmaf(-h, y * y, 1.5f);
    y = y * fmaf(-h, y * y, 1.5f);

    const size_t ob = ((size_t)sf * P + p) * 3;
    out[ob + 0] = px;
    out[ob + 1] = py;
    out[ob + 2] = pz;
    float* on = out + (size_t)SFCOUNT * P * 3;
    on[ob + 0] = nx * y;
    on[ob + 1] = ny * y;
    on[ob + 2] = nz * y;
}

extern "C" void kernel_launch(void* const* d_in, const int* in_sizes, int n_in,
                              void* d_out, int out_size)
{
    const float* ev = (const float*)d_in[0];   // [S,F,P,2] f32
    const float* cp = (const float*)d_in[1];   // [S,F,32,32,3] f32
    float* out = (float*)d_out;                // [2,S,F,P,3] f32 (pt, normals)

    const int P = in_sizes[0] / (SFCOUNT * 2);
    dim3 grid((P + 255) / 256, SFCOUNT);
    nurbs_kernel<<<grid, 256>>>(ev, cp, out, P);
}

// round 9
// speedup vs baseline: 1.3297x; 1.3297x over previous
#include <cuda_runtime.h>
#include <cuda_bf16.h>

// NURBS surface evaluation, degree 3 x 3, 32x32 control points, uniform
// clamped knots. S*F = 32 surface slices, P = 200000 points each.
//
// R4 changes vs R1 (L1TEX was 85.4% -> wavefront reduction):
//  * SoA smem planes: float2 (x,y) + float z, stride 33. Row gather is
//    4x LDS.64 + 4x LDS.32 = 192B/point instead of 16x LDS.128 = 256B/point
//    (the float4 pad lane was pure wasted L1 bandwidth).
//  * 4 points per thread: outputs become 3x STG.128 per array per thread
//    (dense 128B wavefronts) instead of stride-12B STG.32 (3x inflated);
//    inputs become 2x LDG.128.

#define SFCOUNT 32          // S * F
#define NCP     32
#define RSTRIDE 33          // padded row stride (elements)
#define PPT     4           // points per thread

__device__ __forceinline__ void eval_basis(float uu, float b[4], float d[4], int& si_out)
{
    float x  = uu * 29.0f;
    float fs = floorf(x);
    int   si = (int)fs;
    si = max(0, min(si, 28));
    fs = (float)si;

    float t  = x - fs;        // left1
    float r1 = 1.0f - t;      // right1

    // x-domain knots (integers, clamped to [0,29])
    float km1 = (float)max(si - 1, 0);
    float km2 = (float)max(si - 2, 0);
    float kp2 = (float)min(si + 2, 29);
    float kp3 = (float)min(si + 3, 29);
    float left2  = x - km1;
    float left3  = x - km2;
    float right2 = kp2 - x;
    float right3 = kp3 - x;

    // All Cox-de Boor denominators are in {1,2,3}, selected by span.
    bool e0  = (si == 0);
    bool e1  = (si == 1);
    bool e27 = (si == 27);
    bool e28 = (si == 28);
    const float third = 1.0f / 3.0f;
    float inv20 = e0  ? 1.0f : 0.5f;
    float inv21 = e28 ? 1.0f : 0.5f;
    float inv30 = e0  ? 1.0f : (e1  ? 0.5f : third);
    float inv31 = (e0 || e28) ? 0.5f : third;
    float inv32 = e28 ? 1.0f : (e27 ? 0.5f : third);

    // Degree 2 (B1_0 = r1, B1_1 = t)
    float tA  = r1 * inv20;
    float B20 = r1 * tA;
    float sv  = left2 * tA;
    float tB  = t * inv21;
    float B21 = fmaf(right2, tB, sv);
    float B22 = t * tB;

    // Degree 3
    float t0 = B20 * inv30;
    b[0] = r1 * t0;
    sv   = left3 * t0;
    float t1 = B21 * inv31;
    b[1] = fmaf(right2, t1, sv);
    sv   = left2 * t1;
    float t2 = B22 * inv32;
    b[2] = fmaf(right3, t2, sv);
    b[3] = t * t2;

    // Derivative basis (unscaled; global factor cancels in the normal)
    d[0] = -t0;
    d[1] = t0 - t1;
    d[2] = t1 - t2;
    d[3] = t2;

    si_out = si;
}

__global__ __launch_bounds__(256)
void nurbs_kernel(const float* __restrict__ ev,
                  const float* __restrict__ cp,
                  float* __restrict__ out,
                  int P)
{
    __shared__ float2 sxy[NCP * RSTRIDE];   // 8448 B
    __shared__ float  sz [NCP * RSTRIDE];   // 4224 B

    const int sf = blockIdx.y;
    const float* cpb = cp + (size_t)sf * (NCP * NCP * 3);

    // Stage this slice's control points as SoA planes
    for (int k = threadIdx.x; k < NCP * NCP; k += blockDim.x) {
        int iu = k >> 5;
        int iv = k & 31;
        float a  = cpb[3 * k + 0];
        float bb = cpb[3 * k + 1];
        float c  = cpb[3 * k + 2];
        sxy[iu * RSTRIDE + iv] = make_float2(a, bb);
        sz [iu * RSTRIDE + iv] = c;
    }
    __syncthreads();

    const int p0 = (blockIdx.x * blockDim.x + threadIdx.x) * PPT;
    if (p0 >= P) return;

    // Load 4 uv pairs with two float4 loads (32B aligned: p0 % 4 == 0)
    const float4* ev4 = reinterpret_cast<const float4*>(ev + ((size_t)sf * P + p0) * 2);
    float4 e0v = ev4[0];
    float4 e1v = ev4[1];
    float uvu[PPT] = {e0v.x, e0v.z, e1v.x, e1v.z};
    float uvv[PPT] = {e0v.y, e0v.w, e1v.y, e1v.w};

    float4 outpt[3];
    float4 outn [3];
    float* rp = reinterpret_cast<float*>(outpt);
    float* rn = reinterpret_cast<float*>(outn);

#pragma unroll
    for (int q = 0; q < PPT; q++) {
        float bu[4], du[4], bv[4], dv[4];
        int su, svi;
        eval_basis(uvu[q], bu, du, su);
        eval_basis(uvv[q], bv, dv, svi);

        float px = 0.f, py = 0.f, pz = 0.f;
        float ax = 0.f, ay = 0.f, az = 0.f;
        float cx = 0.f, cy = 0.f, cz = 0.f;

        const int base = su * RSTRIDE + svi;
        const float2* bxy = sxy + base;
        const float*  bz  = sz  + base;

#pragma unroll
        for (int i = 0; i < 4; i++) {
            const float2* row = bxy + i * RSTRIDE;
            const float*  rwz = bz  + i * RSTRIDE;
            float2 a0 = row[0];
            float2 a1 = row[1];
            float2 a2 = row[2];
            float2 a3 = row[3];
            float  z0 = rwz[0];
            float  z1 = rwz[1];
            float  z2 = rwz[2];
            float  z3 = rwz[3];

            float rx = fmaf(bv[3], a3.x, fmaf(bv[2], a2.x, fmaf(bv[1], a1.x, bv[0] * a0.x)));
            float ry = fmaf(bv[3], a3.y, fmaf(bv[2], a2.y, fmaf(bv[1], a1.y, bv[0] * a0.y)));
            float rz = fmaf(bv[3], z3,   fmaf(bv[2], z2,   fmaf(bv[1], z1,   bv[0] * z0)));
            float qx = fmaf(dv[3], a3.x, fmaf(dv[2], a2.x, fmaf(dv[1], a1.x, dv[0] * a0.x)));
            float qy = fmaf(dv[3], a3.y, fmaf(dv[2], a2.y, fmaf(dv[1], a1.y, dv[0] * a0.y)));
            float qz = fmaf(dv[3], z3,   fmaf(dv[2], z2,   fmaf(dv[1], z1,   dv[0] * z0)));

            px = fmaf(bu[i], rx, px);
            py = fmaf(bu[i], ry, py);
            pz = fmaf(bu[i], rz, pz);
            ax = fmaf(du[i], rx, ax);
            ay = fmaf(du[i], ry, ay);
            az = fmaf(du[i], rz, az);
            cx = fmaf(bu[i], qx, cx);
            cy = fmaf(bu[i], qy, cy);
            cz = fmaf(bu[i], qz, cz);
        }

        // normal = normalize(cross(d_u, d_v))
        float nx = fmaf(ay, cz, -(az * cy));
        float ny = fmaf(az, cx, -(ax * cz));
        float nz = fmaf(ax, cy, -(ay * cx));

        float n2 = fmaf(nx, nx, fmaf(ny, ny, nz * nz));
        n2 = fmaxf(n2, 1.0e-30f);
        float h = 0.5f * n2;
        float y = __uint_as_float(0x5f3759dfu - (__float_as_uint(n2) >> 1));
        y = y * fmaf(-h, y * y, 1.5f);
        y = y * fmaf(-h, y * y, 1.5f);

        rp[q * 3 + 0] = px;
        rp[q * 3 + 1] = py;
        rp[q * 3 + 2] = pz;
        rn[q * 3 + 0] = nx * y;
        rn[q * 3 + 1] = ny * y;
        rn[q * 3 + 2] = nz * y;
    }

    // Dense 16B stores: 12 floats (4 points x 3) per array, 48B-aligned base
    float4* opt = reinterpret_cast<float4*>(out + ((size_t)sf * P + p0) * 3);
    opt[0] = outpt[0];
    opt[1] = outpt[1];
    opt[2] = outpt[2];
    float4* onr = reinterpret_cast<float4*>(out + (size_t)SFCOUNT * P * 3 +
                                            ((size_t)sf * P + p0) * 3);
    onr[0] = outn[0];
    onr[1] = outn[1];
    onr[2] = outn[2];
}

extern "C" void kernel_launch(void* const* d_in, const int* in_sizes, int n_in,
                              void* d_out, int out_size)
{
    const float* ev = (const float*)d_in[0];   // [S,F,P,2] f32
    const float* cp = (const float*)d_in[1];   // [S,F,32,32,3] f32
    float* out = (float*)d_out;                // [2,S,F,P,3] f32 (pt, normals)

    const int P = in_sizes[0] / (SFCOUNT * 2);
    const int threads_per_slice = (P + PPT - 1) / PPT;
    dim3 grid((threads_per_slice + 255) / 256, SFCOUNT);
    nurbs_kernel<<<grid, 256>>>(ev, cp, out, P);
}